// round 5
// baseline (speedup 1.0000x reference)
#include <cuda_runtime.h>
#include <cuda_bf16.h>
#include <math.h>
#include <stdint.h>

// Problem constants
#define BATCH 32
#define TSTEPS 300
#define CIN   2312        // 34*34*2
#define O1    512
#define O2    512
#define O3    10
#define O3PAD 64
#define MROWS (BATCH*TSTEPS)   // 9600
#define KC    248

// ---------------- static device scratch ----------------
__device__ float g_x1 [ (size_t)BATCH*TSTEPS*CIN ];
__device__ float g_z  [ (size_t)BATCH*TSTEPS*O1  ];
__device__ float g_s1 [ (size_t)BATCH*TSTEPS*O1  ];
__device__ float g_s2 [ (size_t)BATCH*TSTEPS*O2  ];
__device__ float g_W1t[ (size_t)CIN*O1 ];
__device__ float g_W2t[ (size_t)O1*O2 ];
__device__ float g_W3t[ (size_t)O2*O3PAD ];
__device__ unsigned long long g_cnt[3];

// ---------------- init ----------------
__global__ void init_kernel() {
    int tid = blockIdx.x * blockDim.x + threadIdx.x;
    if (tid < 3) g_cnt[tid] = 0ull;
    for (int i = tid; i < O2 * O3PAD; i += gridDim.x * blockDim.x)
        g_W3t[i] = 0.0f;
}

// ---------------- transpose spikes [B,C,T] -> [B,T,C] ----------------
__global__ void transpose_kernel(const float* __restrict__ in) {
    __shared__ float tile[32][33];
    int b  = blockIdx.z;
    int t0 = blockIdx.x * 32;
    int c0 = blockIdx.y * 32;
    int tx = threadIdx.x, ty = threadIdx.y;
    const float* inb = in + (size_t)b * CIN * TSTEPS;
    float* outb = g_x1 + (size_t)b * TSTEPS * CIN;
    int t = t0 + tx;
    #pragma unroll
    for (int j = 0; j < 32; j += 8) {
        int c = c0 + ty + j;
        if (t < TSTEPS && c < CIN)
            tile[ty + j][tx] = inb[(size_t)c * TSTEPS + t];
    }
    __syncthreads();
    int c2 = c0 + tx;
    #pragma unroll
    for (int j = 0; j < 32; j += 8) {
        int t2 = t0 + ty + j;
        if (c2 < CIN && t2 < TSTEPS)
            outb[(size_t)t2 * CIN + c2] = tile[tx][ty + j];
    }
}

// ---------------- weight prep: NEON-style 4-lane vectorized reduce ----------
// Emulates XLA:CPU on aarch64: <4 x float> accumulator over ascending blocks,
// separate mul/add (no contraction), FADDP horizontal: (s0+s1)+(s2+s3).
// C % 4 == 0 for all layers (2312, 512, 512).
__global__ void prep_w_kernel(const float* __restrict__ v, const float* __restrict__ g,
                              float* __restrict__ Wt, int O, int C, int ldw) {
    int o = blockIdx.x * blockDim.x + threadIdx.x;
    if (o >= O) return;
    const float* vr = v + (size_t)o * C;
    float s0 = 0.0f, s1 = 0.0f, s2 = 0.0f, s3 = 0.0f;
    for (int c = 0; c < C; c += 4) {
        float w0 = vr[c + 0], w1 = vr[c + 1], w2 = vr[c + 2], w3 = vr[c + 3];
        s0 = __fadd_rn(s0, __fmul_rn(w0, w0));
        s1 = __fadd_rn(s1, __fmul_rn(w1, w1));
        s2 = __fadd_rn(s2, __fmul_rn(w2, w2));
        s3 = __fadd_rn(s3, __fmul_rn(w3, w3));
    }
    float ssq = __fadd_rn(__fadd_rn(s0, s1), __fadd_rn(s2, s3));
    float norm = sqrtf(ssq);
    float gg = g[o];
    for (int c = 0; c < C; c++) {
        float w = __fdiv_rn(__fmul_rn(gg, vr[c]), norm);
        Wt[(size_t)c * ldw + o] = w;
    }
}

// ---------------- tiled SGEMM with k-panel accumulation ----------
#define BM 128
#define BN 64
#define BK 8

__global__ __launch_bounds__(256)
void sgemm_kernel(const float* __restrict__ A, const float* __restrict__ Bt,
                  float* __restrict__ C, int K, int lda, int ldb, int ldc) {
    __shared__ float As[BK][BM + 4];
    __shared__ float Bs[BK][BN];
    const int tid = threadIdx.x;
    const int m0 = blockIdx.x * BM;
    const int n0 = blockIdx.y * BN;
    const int ty = tid >> 4;
    const int tx = tid & 15;
    const int arow = tid >> 1;
    const int acol = (tid & 1) * 4;
    const int brow = tid >> 5;
    const int bcol = (tid & 31) * 2;

    float accT[8][4];
    #pragma unroll
    for (int i = 0; i < 8; i++)
        #pragma unroll
        for (int j = 0; j < 4; j++) accT[i][j] = 0.0f;

    for (int ps = 0; ps < K; ps += KC) {
        const int pe = (ps + KC < K) ? (ps + KC) : K;
        float accP[8][4];
        #pragma unroll
        for (int i = 0; i < 8; i++)
            #pragma unroll
            for (int j = 0; j < 4; j++) accP[i][j] = 0.0f;

        for (int k0 = ps; k0 < pe; k0 += BK) {
            {
                float4 va = *(const float4*)(A + (size_t)(m0 + arow) * lda + k0 + acol);
                As[acol + 0][arow] = va.x;
                As[acol + 1][arow] = va.y;
                As[acol + 2][arow] = va.z;
                As[acol + 3][arow] = va.w;
            }
            {
                float2 vb = *(const float2*)(Bt + (size_t)(k0 + brow) * ldb + n0 + bcol);
                Bs[brow][bcol + 0] = vb.x;
                Bs[brow][bcol + 1] = vb.y;
            }
            __syncthreads();
            #pragma unroll
            for (int k = 0; k < BK; k++) {
                float a[8], b[4];
                #pragma unroll
                for (int i = 0; i < 8; i++) a[i] = As[k][ty * 8 + i];
                #pragma unroll
                for (int j = 0; j < 4; j++) b[j] = Bs[k][tx * 4 + j];
                #pragma unroll
                for (int i = 0; i < 8; i++)
                    #pragma unroll
                    for (int j = 0; j < 4; j++)
                        accP[i][j] = fmaf(a[i], b[j], accP[i][j]);
            }
            __syncthreads();
        }
        #pragma unroll
        for (int i = 0; i < 8; i++)
            #pragma unroll
            for (int j = 0; j < 4; j++)
                accT[i][j] = __fadd_rn(accT[i][j], accP[i][j]);
    }
    #pragma unroll
    for (int i = 0; i < 8; i++) {
        float4 v = make_float4(accT[i][0], accT[i][1], accT[i][2], accT[i][3]);
        *(float4*)(C + (size_t)(m0 + ty * 8 + i) * ldc + n0 + tx * 4) = v;
    }
}

// ---------------- LIF scan + delay, 512-wide layers ----------------
__global__ void scan512_kernel(const float* __restrict__ z, float* __restrict__ sd,
                               const int* __restrict__ delay, unsigned long long* cnt) {
    int tid = blockIdx.x * blockDim.x + threadIdx.x;  // 16384
    int o = tid & 511;
    int b = tid >> 9;
    int d = delay[o];
    const float* zp = z  + (size_t)b * TSTEPS * 512 + o;
    float*       sp = sd + (size_t)b * TSTEPS * 512 + o;
    float cur = 0.0f, vol = 0.0f;
    unsigned hist = 0u;
    int c = 0;
    for (int t = 0; t < TSTEPS; t++) {
        cur = fmaf(cur, 0.75f, zp[(size_t)t * 512]);
        float v = fmaf(vol, 0.97f, cur);
        int s = (__fadd_rn(v, -1.25f) >= 0.0f);
        vol = s ? 0.0f : v;
        hist = (hist << 1) | (unsigned)s;
        int sv = (t >= d) ? (int)((hist >> d) & 1u) : 0;
        sp[(size_t)t * 512] = (float)sv;
        c += sv;
    }
    atomicAdd(cnt, (unsigned long long)c);
}

// ---------------- LIF scan + delay, output layer ----------------
__global__ void scan_out_kernel(const float* __restrict__ z, float* __restrict__ out,
                                const int* __restrict__ delay, unsigned long long* cnt) {
    int tid = blockIdx.x * blockDim.x + threadIdx.x;
    if (tid >= BATCH * O3) return;
    int o = tid % O3;
    int b = tid / O3;
    int d = delay[o];
    const float* zp = z + (size_t)b * TSTEPS * O3PAD + o;
    float* op = out + (size_t)b * O3 * TSTEPS + (size_t)o * TSTEPS;
    float cur = 0.0f, vol = 0.0f;
    unsigned hist = 0u;
    int c = 0;
    for (int t = 0; t < TSTEPS; t++) {
        cur = fmaf(cur, 0.75f, zp[(size_t)t * O3PAD]);
        float v = fmaf(vol, 0.97f, cur);
        int s = (__fadd_rn(v, -1.25f) >= 0.0f);
        vol = s ? 0.0f : v;
        hist = (hist << 1) | (unsigned)s;
        int sv = (t >= d) ? (int)((hist >> d) & 1u) : 0;
        op[t] = (float)sv;
        c += sv;
    }
    atomicAdd(cnt, (unsigned long long)c);
}

// ---------------- finalize counts ----------------
__global__ void finalize_kernel(float* out) {
    if (threadIdx.x == 0) {
        out[96000] = __fdiv_rn((float)g_cnt[0], 4915200.0f);
        out[96001] = __fdiv_rn((float)g_cnt[1], 4915200.0f);
        out[96002] = __fdiv_rn((float)g_cnt[2], 96000.0f);
    }
}

// ---------------- launch ----------------
extern "C" void kernel_launch(void* const* d_in, const int* in_sizes, int n_in,
                              void* d_out, int out_size) {
    const float* spike = (const float*)d_in[0];
    const float* v1 = (const float*)d_in[1];
    const float* g1 = (const float*)d_in[2];
    const float* v2 = (const float*)d_in[3];
    const float* g2 = (const float*)d_in[4];
    const float* v3 = (const float*)d_in[5];
    const float* g3 = (const float*)d_in[6];
    const int*   d1 = (const int*)d_in[7];
    const int*   d2 = (const int*)d_in[8];
    const int*   d3 = (const int*)d_in[9];
    float* out = (float*)d_out;

    float *x1, *z, *s1, *s2, *W1t, *W2t, *W3t;
    unsigned long long* cnt;
    cudaGetSymbolAddress((void**)&x1,  g_x1);
    cudaGetSymbolAddress((void**)&z,   g_z);
    cudaGetSymbolAddress((void**)&s1,  g_s1);
    cudaGetSymbolAddress((void**)&s2,  g_s2);
    cudaGetSymbolAddress((void**)&W1t, g_W1t);
    cudaGetSymbolAddress((void**)&W2t, g_W2t);
    cudaGetSymbolAddress((void**)&W3t, g_W3t);
    cudaGetSymbolAddress((void**)&cnt, g_cnt);

    init_kernel<<<64, 256>>>();

    {
        dim3 grid((TSTEPS + 31) / 32, (CIN + 31) / 32, BATCH);
        transpose_kernel<<<grid, dim3(32, 8)>>>(spike);
    }

    // layer 1
    prep_w_kernel<<<2, 256>>>(v1, g1, W1t, O1, CIN, O1);
    {
        dim3 grid(MROWS / BM, O1 / BN);
        sgemm_kernel<<<grid, 256>>>(x1, W1t, z, CIN, CIN, O1, O1);
    }
    scan512_kernel<<<(BATCH * O1) / 256, 256>>>(z, s1, d1, cnt + 0);

    // layer 2
    prep_w_kernel<<<2, 256>>>(v2, g2, W2t, O2, O1, O2);
    {
        dim3 grid(MROWS / BM, O2 / BN);
        sgemm_kernel<<<grid, 256>>>(s1, W2t, z, O1, O1, O2, O2);
    }
    scan512_kernel<<<(BATCH * O2) / 256, 256>>>(z, s2, d2, cnt + 1);

    // layer 3 (N padded to 64)
    prep_w_kernel<<<1, 32>>>(v3, g3, W3t, O3, O2, O3PAD);
    {
        dim3 grid(MROWS / BM, O3PAD / BN);
        sgemm_kernel<<<grid, 256>>>(s2, W3t, z, O2, O2, O3PAD, O3PAD);
    }
    scan_out_kernel<<<2, 256>>>(z, out, d3, cnt + 2);

    finalize_kernel<<<1, 32>>>(out);
}

// round 6
// speedup vs baseline: 1.6058x; 1.6058x over previous
#include <cuda_runtime.h>
#include <cuda_bf16.h>
#include <math.h>
#include <stdint.h>

// Problem constants
#define BATCH 32
#define TSTEPS 300
#define CIN   2312        // 34*34*2
#define O1    512
#define O2    512
#define O3    10
#define O3PAD 64
#define MROWS (BATCH*TSTEPS)   // 9600
#define KC    248
#define NPMAX 10

// ---------------- static device scratch ----------------
__device__ float g_x1 [ (size_t)BATCH*TSTEPS*CIN ];
__device__ float g_z  [ (size_t)BATCH*TSTEPS*O1  ];
__device__ float g_s1 [ (size_t)BATCH*TSTEPS*O1  ];
__device__ float g_s2 [ (size_t)BATCH*TSTEPS*O2  ];
__device__ float g_W1t[ (size_t)CIN*O1 ];
__device__ float g_W2t[ (size_t)O1*O2 ];
__device__ float g_W3t[ (size_t)O2*O3PAD ];
__device__ float g_norm[512];
__device__ unsigned short g_idx1[(size_t)MROWS*CIN];   // layer1 nz lists
__device__ unsigned short g_idx2[(size_t)MROWS*O1];    // layer2/3 nz lists (reused)
__device__ int g_cntP[(size_t)MROWS*NPMAX];
__device__ unsigned long long g_cnt[3];

// ---------------- init: zero counters + padded W3 ----------------
__global__ void init_kernel() {
    int tid = blockIdx.x * blockDim.x + threadIdx.x;
    if (tid < 3) g_cnt[tid] = 0ull;
    for (int i = tid; i < O2 * O3PAD; i += gridDim.x * blockDim.x)
        g_W3t[i] = 0.0f;
}

// ---------------- transpose spikes [B,C,T] -> [B,T,C] ----------------
__global__ void transpose_kernel(const float* __restrict__ in) {
    __shared__ float tile[32][33];
    int b  = blockIdx.z;
    int t0 = blockIdx.x * 32;
    int c0 = blockIdx.y * 32;
    int tx = threadIdx.x, ty = threadIdx.y;
    const float* inb = in + (size_t)b * CIN * TSTEPS;
    float* outb = g_x1 + (size_t)b * TSTEPS * CIN;
    int t = t0 + tx;
    #pragma unroll
    for (int j = 0; j < 32; j += 8) {
        int c = c0 + ty + j;
        if (t < TSTEPS && c < CIN)
            tile[ty + j][tx] = inb[(size_t)c * TSTEPS + t];
    }
    __syncthreads();
    int c2 = c0 + tx;
    #pragma unroll
    for (int j = 0; j < 32; j += 8) {
        int t2 = t0 + ty + j;
        if (c2 < CIN && t2 < TSTEPS)
            outb[(size_t)t2 * CIN + c2] = tile[tx][ty + j];
    }
}

// ---------------- norm: NEON 4-lane reduce, 4 threads per row -------------
// Bit-identical to passing version: s_j over c=j,j+4,..., then (s0+s1)+(s2+s3).
__global__ void norm4_kernel(const float* __restrict__ v, float* __restrict__ nrm,
                             int O, int C) {
    int t = blockIdx.x * blockDim.x + threadIdx.x;
    int j = t & 3;
    int o = t >> 2;
    int oc = (o < O) ? o : (O - 1);        // clamp loads, keep groups converged
    const float* vr = v + (size_t)oc * C;
    float s = 0.0f;
    for (int c = j; c < C; c += 4)
        s = __fadd_rn(s, __fmul_rn(vr[c], vr[c]));
    unsigned gm = 0xFu << ((((unsigned)t & 31u) >> 2) << 2);
    float u  = __shfl_down_sync(gm, s, 1, 4);
    float a  = __fadd_rn(s, u);            // j=0: s0+s1 ; j=2: s2+s3
    float b2 = __shfl_down_sync(gm, a, 2, 4);
    if (j == 0 && o < O) nrm[o] = sqrtf(__fadd_rn(a, b2));
}

// ---------------- scale + transpose: Wt[c][o] = fdiv(fmul(g,v), norm) ------
__global__ void scale_kernel(const float* __restrict__ v, const float* __restrict__ g,
                             const float* __restrict__ nrm, float* __restrict__ Wt,
                             int O, int C, int ldw) {
    __shared__ float tile[32][33];
    int c0 = blockIdx.x * 32, o0 = blockIdx.y * 32;
    int tx = threadIdx.x, ty = threadIdx.y;  // (32,8)
    #pragma unroll
    for (int jj = 0; jj < 32; jj += 8) {
        int o = o0 + ty + jj, c = c0 + tx;
        if (o < O && c < C)
            tile[ty + jj][tx] = __fdiv_rn(__fmul_rn(g[o], v[(size_t)o * C + c]), nrm[o]);
    }
    __syncthreads();
    #pragma unroll
    for (int jj = 0; jj < 32; jj += 8) {
        int c = c0 + ty + jj, o = o0 + tx;
        if (o < O && c < C)
            Wt[(size_t)c * ldw + o] = tile[tx][ty + jj];
    }
}

// ---------------- build nonzero index lists (warp per row) -----------------
__global__ void build_kernel(const float* __restrict__ x, unsigned short* __restrict__ idx,
                             int* __restrict__ cntP, int K, int NP) {
    int warp = threadIdx.x >> 5, lane = threadIdx.x & 31;
    int row = blockIdx.x * 8 + warp;       // block 256 = 8 warps
    const float* xr = x + (size_t)row * K;
    unsigned short* ir = idx + (size_t)row * K;
    int pos = 0; int pcnt = 0;
    for (int k0 = 0; k0 < K; k0 += 32) {
        int k = k0 + lane;
        float vv = (k < K) ? xr[k] : 0.0f;
        unsigned m = __ballot_sync(0xffffffffu, vv != 0.0f);
        if (vv != 0.0f) {
            int off = pos + __popc(m & ((1u << lane) - 1u));
            ir[off] = (unsigned short)k;
        }
        int p0 = k0 / KC, p1 = (k0 + 31) / KC;
        if (p0 == p1) {
            if (lane == p0) pcnt += __popc(m);
        } else {
            int bnd = p1 * KC;
            unsigned low = (1u << (bnd - k0)) - 1u;
            if (lane == p0) pcnt += __popc(m & low);
            if (lane == p1) pcnt += __popc(m & ~low);
        }
        pos += __popc(m);
    }
    if (lane < NP) cntP[row * NPMAX + lane] = pcnt;
}

// ---------------- sparse accumulate: Z[row, o] = sum_{c in nz(row)} W[c][o] --
// Bit-exact emulation of the dense panel GEMM: per panel ascending-c fadd chain
// (fmaf(1,w,acc)==fadd(acc,w); fmaf(0,w,acc)==acc), panels combined by fadd.
#define RPB 128     // rows per block
#define OT  64      // output columns per block
#define RPW 16      // rows per walker (8 walkers x 64 o-threads = 512)

extern __shared__ float Ws[];   // [248][OT]

__global__ __launch_bounds__(512)
void spmm_kernel(const unsigned short* __restrict__ idx, const int* __restrict__ cntP,
                 const float* __restrict__ W, float* __restrict__ Z,
                 int K, int NP, int ldw, int ldc) {
    const int tid = threadIdx.x;
    const int o = tid & 63;
    const int w = tid >> 6;
    const int row0 = blockIdx.x * RPB + w * RPW;
    const int o0 = blockIdx.y * OT;

    float acc[RPW];
    int pos[RPW];
    #pragma unroll
    for (int j = 0; j < RPW; j++) { acc[j] = 0.0f; pos[j] = 0; }

    for (int p = 0; p < NP; p++) {
        int ps = p * KC;
        int prows = K - ps; if (prows > KC) prows = KC;
        // cooperative panel load: W[ps..ps+prows) x [o0..o0+64)
        for (int i4 = tid; i4 < prows * (OT / 4); i4 += 512) {
            int r = i4 >> 4, c4 = (i4 & 15) << 2;
            float4 vv = *(const float4*)(W + (size_t)(ps + r) * ldw + o0 + c4);
            *(float4*)&Ws[r * OT + c4] = vv;
        }
        __syncthreads();
        int cnts[RPW];
        #pragma unroll
        for (int j = 0; j < RPW; j++)
            cnts[j] = cntP[(row0 + j) * NPMAX + p];
        #pragma unroll 1
        for (int j = 0; j < RPW; j++) {
            const unsigned short* ip = idx + (size_t)(row0 + j) * K + pos[j];
            int cnt = cnts[j];
            float accP = 0.0f;
            for (int i = 0; i < cnt; i++) {
                int c = ip[i];
                accP = __fadd_rn(accP, Ws[(c - ps) * OT + o]);
            }
            pos[j] += cnt;
            acc[j] = __fadd_rn(acc[j], accP);
        }
        __syncthreads();
    }
    #pragma unroll
    for (int j = 0; j < RPW; j++)
        Z[(size_t)(row0 + j) * ldc + o0 + o] = acc[j];
}

// ---------------- LIF scan + delay, 512-wide layers ----------------
__global__ void scan512_kernel(const float* __restrict__ z, float* __restrict__ sd,
                               const int* __restrict__ delay, unsigned long long* cnt) {
    int tid = blockIdx.x * blockDim.x + threadIdx.x;  // 16384
    int o = tid & 511;
    int b = tid >> 9;
    int d = delay[o];
    const float* zp = z  + (size_t)b * TSTEPS * 512 + o;
    float*       sp = sd + (size_t)b * TSTEPS * 512 + o;
    float cur = 0.0f, vol = 0.0f;
    unsigned hist = 0u;
    int c = 0;
    for (int t = 0; t < TSTEPS; t++) {
        cur = fmaf(cur, 0.75f, zp[(size_t)t * 512]);
        float v = fmaf(vol, 0.97f, cur);
        int s = (__fadd_rn(v, -1.25f) >= 0.0f);
        vol = s ? 0.0f : v;
        hist = (hist << 1) | (unsigned)s;
        int sv = (t >= d) ? (int)((hist >> d) & 1u) : 0;
        sp[(size_t)t * 512] = (float)sv;
        c += sv;
    }
    atomicAdd(cnt, (unsigned long long)c);
}

// ---------------- LIF scan + delay, output layer ----------------
__global__ void scan_out_kernel(const float* __restrict__ z, float* __restrict__ out,
                                const int* __restrict__ delay, unsigned long long* cnt) {
    int tid = blockIdx.x * blockDim.x + threadIdx.x;
    if (tid >= BATCH * O3) return;
    int o = tid % O3;
    int b = tid / O3;
    int d = delay[o];
    const float* zp = z + (size_t)b * TSTEPS * O3PAD + o;
    float* op = out + (size_t)b * O3 * TSTEPS + (size_t)o * TSTEPS;
    float cur = 0.0f, vol = 0.0f;
    unsigned hist = 0u;
    int c = 0;
    for (int t = 0; t < TSTEPS; t++) {
        cur = fmaf(cur, 0.75f, zp[(size_t)t * O3PAD]);
        float v = fmaf(vol, 0.97f, cur);
        int s = (__fadd_rn(v, -1.25f) >= 0.0f);
        vol = s ? 0.0f : v;
        hist = (hist << 1) | (unsigned)s;
        int sv = (t >= d) ? (int)((hist >> d) & 1u) : 0;
        op[t] = (float)sv;
        c += sv;
    }
    atomicAdd(cnt, (unsigned long long)c);
}

// ---------------- finalize counts ----------------
__global__ void finalize_kernel(float* out) {
    if (threadIdx.x == 0) {
        out[96000] = __fdiv_rn((float)g_cnt[0], 4915200.0f);
        out[96001] = __fdiv_rn((float)g_cnt[1], 4915200.0f);
        out[96002] = __fdiv_rn((float)g_cnt[2], 96000.0f);
    }
}

// ---------------- launch ----------------
extern "C" void kernel_launch(void* const* d_in, const int* in_sizes, int n_in,
                              void* d_out, int out_size) {
    const float* spike = (const float*)d_in[0];
    const float* v1 = (const float*)d_in[1];
    const float* g1 = (const float*)d_in[2];
    const float* v2 = (const float*)d_in[3];
    const float* g2 = (const float*)d_in[4];
    const float* v3 = (const float*)d_in[5];
    const float* g3 = (const float*)d_in[6];
    const int*   d1 = (const int*)d_in[7];
    const int*   d2 = (const int*)d_in[8];
    const int*   d3 = (const int*)d_in[9];
    float* out = (float*)d_out;

    float *x1, *z, *s1, *s2, *W1t, *W2t, *W3t, *nrm;
    unsigned short *idx1, *idx2;
    int* cntP;
    unsigned long long* cnt;
    cudaGetSymbolAddress((void**)&x1,  g_x1);
    cudaGetSymbolAddress((void**)&z,   g_z);
    cudaGetSymbolAddress((void**)&s1,  g_s1);
    cudaGetSymbolAddress((void**)&s2,  g_s2);
    cudaGetSymbolAddress((void**)&W1t, g_W1t);
    cudaGetSymbolAddress((void**)&W2t, g_W2t);
    cudaGetSymbolAddress((void**)&W3t, g_W3t);
    cudaGetSymbolAddress((void**)&nrm, g_norm);
    cudaGetSymbolAddress((void**)&idx1, g_idx1);
    cudaGetSymbolAddress((void**)&idx2, g_idx2);
    cudaGetSymbolAddress((void**)&cntP, g_cntP);
    cudaGetSymbolAddress((void**)&cnt, g_cnt);

    static int smem_set = 0;
    if (!smem_set) {
        cudaFuncSetAttribute(spmm_kernel, cudaFuncAttributeMaxDynamicSharedMemorySize,
                             KC * OT * (int)sizeof(float));
        smem_set = 1;
    }
    const int SPMM_SMEM = KC * OT * (int)sizeof(float);  // 63488

    init_kernel<<<64, 256>>>();

    {
        dim3 grid((TSTEPS + 31) / 32, (CIN + 31) / 32, BATCH);
        transpose_kernel<<<grid, dim3(32, 8)>>>(spike);
    }

    // ---- layer 1 ----
    norm4_kernel<<<(O1 * 4) / 256, 256>>>(v1, nrm, O1, CIN);
    scale_kernel<<<dim3((CIN + 31) / 32, O1 / 32), dim3(32, 8)>>>(v1, g1, nrm, W1t, O1, CIN, O1);
    build_kernel<<<MROWS / 8, 256>>>(x1, idx1, cntP, CIN, 10);
    spmm_kernel<<<dim3(MROWS / RPB, O1 / OT), 512, SPMM_SMEM>>>(idx1, cntP, W1t, z, CIN, 10, O1, O1);
    scan512_kernel<<<(BATCH * O1) / 256, 256>>>(z, s1, d1, cnt + 0);

    // ---- layer 2 ----
    norm4_kernel<<<(O2 * 4) / 256, 256>>>(v2, nrm, O2, O1);
    scale_kernel<<<dim3(O1 / 32, O2 / 32), dim3(32, 8)>>>(v2, g2, nrm, W2t, O2, O1, O2);
    build_kernel<<<MROWS / 8, 256>>>(s1, idx2, cntP, O1, 3);
    spmm_kernel<<<dim3(MROWS / RPB, O2 / OT), 512, SPMM_SMEM>>>(idx2, cntP, W2t, z, O1, 3, O2, O2);
    scan512_kernel<<<(BATCH * O2) / 256, 256>>>(z, s2, d2, cnt + 1);

    // ---- layer 3 (N padded to 64) ----
    norm4_kernel<<<1, 128>>>(v3, nrm, O3, O2);
    scale_kernel<<<dim3(O2 / 32, 1), dim3(32, 8)>>>(v3, g3, nrm, W3t, O3, O2, O3PAD);
    build_kernel<<<MROWS / 8, 256>>>(s2, idx2, cntP, O2, 3);
    spmm_kernel<<<dim3(MROWS / RPB, 1), 512, SPMM_SMEM>>>(idx2, cntP, W3t, z, O2, 3, O3PAD, O3PAD);
    scan_out_kernel<<<2, 256>>>(z, out, d3, cnt + 2);

    finalize_kernel<<<1, 32>>>(out);
}

// round 7
// speedup vs baseline: 2.1407x; 1.3331x over previous
#include <cuda_runtime.h>
#include <cuda_bf16.h>
#include <math.h>
#include <stdint.h>

// Problem constants
#define BATCH 32
#define TSTEPS 300
#define CIN   2312        // 34*34*2
#define O1    512
#define O2    512
#define O3    10
#define O3PAD 64
#define MROWS (BATCH*TSTEPS)   // 9600
#define KC    248
#define NPMAX 10

// ---------------- static device scratch ----------------
__device__ float g_x1 [ (size_t)BATCH*TSTEPS*CIN ];
__device__ float g_z  [ (size_t)BATCH*TSTEPS*O1  ];
__device__ float g_s1 [ (size_t)BATCH*TSTEPS*O1  ];
__device__ float g_s2 [ (size_t)BATCH*TSTEPS*O2  ];
__device__ float g_W1t[ (size_t)CIN*O1 ];
__device__ float g_W2t[ (size_t)O1*O2 ];
__device__ float g_W3t[ (size_t)O2*O3PAD ];
__device__ float g_norm[512];
__device__ unsigned short g_idx1[(size_t)MROWS*CIN];   // layer1 nz lists
__device__ unsigned short g_idx2[(size_t)MROWS*O1];    // layer2/3 nz lists (reused)
__device__ int g_cntP[(size_t)MROWS*NPMAX];
__device__ unsigned long long g_cnt[3];

// ---------------- init: zero counters + padded W3 ----------------
__global__ void init_kernel() {
    int tid = blockIdx.x * blockDim.x + threadIdx.x;
    if (tid < 3) g_cnt[tid] = 0ull;
    for (int i = tid; i < O2 * O3PAD; i += gridDim.x * blockDim.x)
        g_W3t[i] = 0.0f;
}

// ---------------- transpose spikes [B,C,T] -> [B,T,C] ----------------
__global__ void transpose_kernel(const float* __restrict__ in) {
    __shared__ float tile[32][33];
    int b  = blockIdx.z;
    int t0 = blockIdx.x * 32;
    int c0 = blockIdx.y * 32;
    int tx = threadIdx.x, ty = threadIdx.y;
    const float* inb = in + (size_t)b * CIN * TSTEPS;
    float* outb = g_x1 + (size_t)b * TSTEPS * CIN;
    int t = t0 + tx;
    #pragma unroll
    for (int j = 0; j < 32; j += 8) {
        int c = c0 + ty + j;
        if (t < TSTEPS && c < CIN)
            tile[ty + j][tx] = inb[(size_t)c * TSTEPS + t];
    }
    __syncthreads();
    int c2 = c0 + tx;
    #pragma unroll
    for (int j = 0; j < 32; j += 8) {
        int t2 = t0 + ty + j;
        if (c2 < CIN && t2 < TSTEPS)
            outb[(size_t)t2 * CIN + c2] = tile[tx][ty + j];
    }
}

// ---------------- norm: NEON 4-lane reduce, 4 threads per row -------------
__global__ void norm4_kernel(const float* __restrict__ v, float* __restrict__ nrm,
                             int O, int C) {
    int t = blockIdx.x * blockDim.x + threadIdx.x;
    int j = t & 3;
    int o = t >> 2;
    int oc = (o < O) ? o : (O - 1);
    const float* vr = v + (size_t)oc * C;
    float s = 0.0f;
    for (int c = j; c < C; c += 4)
        s = __fadd_rn(s, __fmul_rn(vr[c], vr[c]));
    unsigned gm = 0xFu << ((((unsigned)t & 31u) >> 2) << 2);
    float u  = __shfl_down_sync(gm, s, 1, 4);
    float a  = __fadd_rn(s, u);
    float b2 = __shfl_down_sync(gm, a, 2, 4);
    if (j == 0 && o < O) nrm[o] = sqrtf(__fadd_rn(a, b2));
}

// ---------------- scale + transpose: Wt[c][o] = fdiv(fmul(g,v), norm) ------
__global__ void scale_kernel(const float* __restrict__ v, const float* __restrict__ g,
                             const float* __restrict__ nrm, float* __restrict__ Wt,
                             int O, int C, int ldw) {
    __shared__ float tile[32][33];
    int c0 = blockIdx.x * 32, o0 = blockIdx.y * 32;
    int tx = threadIdx.x, ty = threadIdx.y;
    #pragma unroll
    for (int jj = 0; jj < 32; jj += 8) {
        int o = o0 + ty + jj, c = c0 + tx;
        if (o < O && c < C)
            tile[ty + jj][tx] = __fdiv_rn(__fmul_rn(g[o], v[(size_t)o * C + c]), nrm[o]);
    }
    __syncthreads();
    #pragma unroll
    for (int jj = 0; jj < 32; jj += 8) {
        int c = c0 + ty + jj, o = o0 + tx;
        if (o < O && c < C)
            Wt[(size_t)c * ldw + o] = tile[tx][ty + jj];
    }
}

// ---------------- build nonzero index lists (warp per row) -----------------
__global__ void build_kernel(const float* __restrict__ x, unsigned short* __restrict__ idx,
                             int* __restrict__ cntP, int K, int NP) {
    int warp = threadIdx.x >> 5, lane = threadIdx.x & 31;
    int row = blockIdx.x * 8 + warp;
    const float* xr = x + (size_t)row * K;
    unsigned short* ir = idx + (size_t)row * K;
    int pos = 0; int pcnt = 0;
    for (int k0 = 0; k0 < K; k0 += 32) {
        int k = k0 + lane;
        float vv = (k < K) ? xr[k] : 0.0f;
        unsigned m = __ballot_sync(0xffffffffu, vv != 0.0f);
        if (vv != 0.0f) {
            int off = pos + __popc(m & ((1u << lane) - 1u));
            ir[off] = (unsigned short)k;
        }
        int p0 = k0 / KC, p1 = (k0 + 31) / KC;
        if (p0 == p1) {
            if (lane == p0) pcnt += __popc(m);
        } else {
            int bnd = p1 * KC;
            unsigned low = (1u << (bnd - k0)) - 1u;
            if (lane == p0) pcnt += __popc(m & low);
            if (lane == p1) pcnt += __popc(m & ~low);
        }
        pos += __popc(m);
    }
    if (lane < NP) cntP[row * NPMAX + lane] = pcnt;
}

// ---------------- sparse accumulate v2 ------------------------------------
// Z[row, o] = sum_{c in nz(row)} W[c][o], bit-exact panel structure.
// Block: 512 threads = 16 warps; tile = 128 rows x 64 cols.
// Each warp owns 8 rows and the FULL 64-col tile (2 cols/thread via LDS.64),
// so each row is walked once per warp (8x fewer walks than v1 grouping).
#define RPB 128     // rows per block
#define OT  64      // output columns per block
#define RPW 8       // rows per warp

extern __shared__ float Ws[];   // [KC][OT]

__global__ __launch_bounds__(512)
void spmm_kernel(const unsigned short* __restrict__ idx, const int* __restrict__ cntP,
                 const float* __restrict__ W, float* __restrict__ Z,
                 int K, int NP, int ldw, int ldc) {
    const int tid  = threadIdx.x;
    const int lane = tid & 31;
    const int warp = tid >> 5;               // 0..15
    const int row0 = blockIdx.x * RPB + warp * RPW;
    const int o0   = blockIdx.y * OT;
    const int ocol = lane * 2;               // thread's column pair within tile

    float2 acc[RPW];
    int pos[RPW];
    #pragma unroll
    for (int j = 0; j < RPW; j++) { acc[j] = make_float2(0.f, 0.f); pos[j] = 0; }

    for (int p = 0; p < NP; p++) {
        int ps = p * KC;
        int prows = K - ps; if (prows > KC) prows = KC;
        // cooperative panel load: W[ps..ps+prows) x [o0..o0+64)
        for (int i4 = tid; i4 < prows * (OT / 4); i4 += 512) {
            int r = i4 >> 4, c4 = (i4 & 15) << 2;
            float4 vv = *(const float4*)(W + (size_t)(ps + r) * ldw + o0 + c4);
            *(float4*)&Ws[r * OT + c4] = vv;
        }
        __syncthreads();
        #pragma unroll 1
        for (int j = 0; j < RPW; j++) {
            const int row = row0 + j;
            const int cnt = cntP[row * NPMAX + p];
            const unsigned short* ip = idx + (size_t)row * K + pos[j];
            float ax = 0.0f, ay = 0.0f;
            for (int i = 0; i < cnt; i++) {
                int c = ip[i];
                float2 wv = *(const float2*)&Ws[(c - ps) * OT + ocol];
                ax = __fadd_rn(ax, wv.x);
                ay = __fadd_rn(ay, wv.y);
            }
            pos[j] += cnt;
            acc[j].x = __fadd_rn(acc[j].x, ax);
            acc[j].y = __fadd_rn(acc[j].y, ay);
        }
        __syncthreads();
    }
    #pragma unroll
    for (int j = 0; j < RPW; j++)
        *(float2*)(Z + (size_t)(row0 + j) * ldc + o0 + ocol) = acc[j];
}

// ---------------- LIF scan + delay, 512-wide layers ----------------
__global__ void scan512_kernel(const float* __restrict__ z, float* __restrict__ sd,
                               const int* __restrict__ delay, unsigned long long* cnt) {
    int tid = blockIdx.x * blockDim.x + threadIdx.x;  // 16384
    int o = tid & 511;
    int b = tid >> 9;
    int d = delay[o];
    const float* zp = z  + (size_t)b * TSTEPS * 512 + o;
    float*       sp = sd + (size_t)b * TSTEPS * 512 + o;
    float cur = 0.0f, vol = 0.0f;
    unsigned hist = 0u;
    int c = 0;
    for (int t = 0; t < TSTEPS; t++) {
        cur = fmaf(cur, 0.75f, zp[(size_t)t * 512]);
        float v = fmaf(vol, 0.97f, cur);
        int s = (__fadd_rn(v, -1.25f) >= 0.0f);
        vol = s ? 0.0f : v;
        hist = (hist << 1) | (unsigned)s;
        int sv = (t >= d) ? (int)((hist >> d) & 1u) : 0;
        sp[(size_t)t * 512] = (float)sv;
        c += sv;
    }
    atomicAdd(cnt, (unsigned long long)c);
}

// ---------------- LIF scan + delay, output layer ----------------
__global__ void scan_out_kernel(const float* __restrict__ z, float* __restrict__ out,
                                const int* __restrict__ delay, unsigned long long* cnt) {
    int tid = blockIdx.x * blockDim.x + threadIdx.x;
    if (tid >= BATCH * O3) return;
    int o = tid % O3;
    int b = tid / O3;
    int d = delay[o];
    const float* zp = z + (size_t)b * TSTEPS * O3PAD + o;
    float* op = out + (size_t)b * O3 * TSTEPS + (size_t)o * TSTEPS;
    float cur = 0.0f, vol = 0.0f;
    unsigned hist = 0u;
    int c = 0;
    for (int t = 0; t < TSTEPS; t++) {
        cur = fmaf(cur, 0.75f, zp[(size_t)t * O3PAD]);
        float v = fmaf(vol, 0.97f, cur);
        int s = (__fadd_rn(v, -1.25f) >= 0.0f);
        vol = s ? 0.0f : v;
        hist = (hist << 1) | (unsigned)s;
        int sv = (t >= d) ? (int)((hist >> d) & 1u) : 0;
        op[t] = (float)sv;
        c += sv;
    }
    atomicAdd(cnt, (unsigned long long)c);
}

// ---------------- finalize counts ----------------
__global__ void finalize_kernel(float* out) {
    if (threadIdx.x == 0) {
        out[96000] = __fdiv_rn((float)g_cnt[0], 4915200.0f);
        out[96001] = __fdiv_rn((float)g_cnt[1], 4915200.0f);
        out[96002] = __fdiv_rn((float)g_cnt[2], 96000.0f);
    }
}

// ---------------- launch ----------------
extern "C" void kernel_launch(void* const* d_in, const int* in_sizes, int n_in,
                              void* d_out, int out_size) {
    const float* spike = (const float*)d_in[0];
    const float* v1 = (const float*)d_in[1];
    const float* g1 = (const float*)d_in[2];
    const float* v2 = (const float*)d_in[3];
    const float* g2 = (const float*)d_in[4];
    const float* v3 = (const float*)d_in[5];
    const float* g3 = (const float*)d_in[6];
    const int*   d1 = (const int*)d_in[7];
    const int*   d2 = (const int*)d_in[8];
    const int*   d3 = (const int*)d_in[9];
    float* out = (float*)d_out;

    float *x1, *z, *s1, *s2, *W1t, *W2t, *W3t, *nrm;
    unsigned short *idx1, *idx2;
    int* cntP;
    unsigned long long* cnt;
    cudaGetSymbolAddress((void**)&x1,  g_x1);
    cudaGetSymbolAddress((void**)&z,   g_z);
    cudaGetSymbolAddress((void**)&s1,  g_s1);
    cudaGetSymbolAddress((void**)&s2,  g_s2);
    cudaGetSymbolAddress((void**)&W1t, g_W1t);
    cudaGetSymbolAddress((void**)&W2t, g_W2t);
    cudaGetSymbolAddress((void**)&W3t, g_W3t);
    cudaGetSymbolAddress((void**)&nrm, g_norm);
    cudaGetSymbolAddress((void**)&idx1, g_idx1);
    cudaGetSymbolAddress((void**)&idx2, g_idx2);
    cudaGetSymbolAddress((void**)&cntP, g_cntP);
    cudaGetSymbolAddress((void**)&cnt, g_cnt);

    static int smem_set = 0;
    if (!smem_set) {
        cudaFuncSetAttribute(spmm_kernel, cudaFuncAttributeMaxDynamicSharedMemorySize,
                             KC * OT * (int)sizeof(float));
        smem_set = 1;
    }
    const int SPMM_SMEM = KC * OT * (int)sizeof(float);  // 63488

    init_kernel<<<64, 256>>>();

    {
        dim3 grid((TSTEPS + 31) / 32, (CIN + 31) / 32, BATCH);
        transpose_kernel<<<grid, dim3(32, 8)>>>(spike);
    }

    // ---- layer 1 ----
    norm4_kernel<<<(O1 * 4) / 256, 256>>>(v1, nrm, O1, CIN);
    scale_kernel<<<dim3((CIN + 31) / 32, O1 / 32), dim3(32, 8)>>>(v1, g1, nrm, W1t, O1, CIN, O1);
    build_kernel<<<MROWS / 8, 256>>>(x1, idx1, cntP, CIN, 10);
    spmm_kernel<<<dim3(MROWS / RPB, O1 / OT), 512, SPMM_SMEM>>>(idx1, cntP, W1t, z, CIN, 10, O1, O1);
    scan512_kernel<<<(BATCH * O1) / 256, 256>>>(z, s1, d1, cnt + 0);

    // ---- layer 2 ----
    norm4_kernel<<<(O2 * 4) / 256, 256>>>(v2, nrm, O2, O1);
    scale_kernel<<<dim3(O1 / 32, O2 / 32), dim3(32, 8)>>>(v2, g2, nrm, W2t, O2, O1, O2);
    build_kernel<<<MROWS / 8, 256>>>(s1, idx2, cntP, O1, 3);
    spmm_kernel<<<dim3(MROWS / RPB, O2 / OT), 512, SPMM_SMEM>>>(idx2, cntP, W2t, z, O1, 3, O2, O2);
    scan512_kernel<<<(BATCH * O2) / 256, 256>>>(z, s2, d2, cnt + 1);

    // ---- layer 3 (N padded to 64) ----
    norm4_kernel<<<1, 128>>>(v3, nrm, O3, O2);
    scale_kernel<<<dim3(O2 / 32, 1), dim3(32, 8)>>>(v3, g3, nrm, W3t, O3, O2, O3PAD);
    build_kernel<<<MROWS / 8, 256>>>(s2, idx2, cntP, O2, 3);
    spmm_kernel<<<dim3(MROWS / RPB, 1), 512, SPMM_SMEM>>>(idx2, cntP, W3t, z, O2, 3, O3PAD, O3PAD);
    scan_out_kernel<<<2, 256>>>(z, out, d3, cnt + 2);

    finalize_kernel<<<1, 32>>>(out);
}

// round 8
// speedup vs baseline: 2.4417x; 1.1406x over previous
#include <cuda_runtime.h>
#include <cuda_bf16.h>
#include <math.h>
#include <stdint.h>

// Problem constants
#define BATCH 32
#define TSTEPS 300
#define CIN   2312        // 34*34*2
#define O1    512
#define O2    512
#define O3    10
#define O3PAD 128         // pad layer3 W to OT columns
#define MROWS (BATCH*TSTEPS)   // 9600
#define KC    248         // Eigen accumulation panel (bit-exactness anchor)
#define SC    124         // smem staging sub-panel (2 per KC panel)
#define NSMAX 19          // max subchunks: ceil(2312/124)

// ---------------- static device scratch ----------------
__device__ float g_x1 [ (size_t)BATCH*TSTEPS*CIN ];
__device__ float g_z  [ (size_t)BATCH*TSTEPS*O1  ];
__device__ float g_s1 [ (size_t)BATCH*TSTEPS*O1  ];
__device__ float g_s2 [ (size_t)BATCH*TSTEPS*O2  ];
__device__ float g_W1t[ (size_t)CIN*O1 ];
__device__ float g_W2t[ (size_t)O1*O2 ];
__device__ float g_W3t[ (size_t)O2*O3PAD ];
__device__ float g_norm[512];
__device__ unsigned short g_idx1[(size_t)MROWS*CIN];
__device__ unsigned short g_idx2[(size_t)MROWS*O1];
__device__ int g_cntS[(size_t)MROWS*NSMAX];
__device__ unsigned long long g_cnt[3];

// ---------------- init: zero counters + padded W3 ----------------
__global__ void init_kernel() {
    int tid = blockIdx.x * blockDim.x + threadIdx.x;
    if (tid < 3) g_cnt[tid] = 0ull;
    for (int i = tid; i < O2 * O3PAD; i += gridDim.x * blockDim.x)
        g_W3t[i] = 0.0f;
}

// ---------------- transpose spikes [B,C,T] -> [B,T,C] ----------------
__global__ void transpose_kernel(const float* __restrict__ in) {
    __shared__ float tile[32][33];
    int b  = blockIdx.z;
    int t0 = blockIdx.x * 32;
    int c0 = blockIdx.y * 32;
    int tx = threadIdx.x, ty = threadIdx.y;
    const float* inb = in + (size_t)b * CIN * TSTEPS;
    float* outb = g_x1 + (size_t)b * TSTEPS * CIN;
    int t = t0 + tx;
    #pragma unroll
    for (int j = 0; j < 32; j += 8) {
        int c = c0 + ty + j;
        if (t < TSTEPS && c < CIN)
            tile[ty + j][tx] = inb[(size_t)c * TSTEPS + t];
    }
    __syncthreads();
    int c2 = c0 + tx;
    #pragma unroll
    for (int j = 0; j < 32; j += 8) {
        int t2 = t0 + ty + j;
        if (c2 < CIN && t2 < TSTEPS)
            outb[(size_t)t2 * CIN + c2] = tile[tx][ty + j];
    }
}

// ---------------- norm: NEON 4-lane reduce, 4 threads per row -------------
__global__ void norm4_kernel(const float* __restrict__ v, float* __restrict__ nrm,
                             int O, int C) {
    int t = blockIdx.x * blockDim.x + threadIdx.x;
    int j = t & 3;
    int o = t >> 2;
    int oc = (o < O) ? o : (O - 1);
    const float* vr = v + (size_t)oc * C;
    float s = 0.0f;
    for (int c = j; c < C; c += 4)
        s = __fadd_rn(s, __fmul_rn(vr[c], vr[c]));
    unsigned gm = 0xFu << ((((unsigned)t & 31u) >> 2) << 2);
    float u  = __shfl_down_sync(gm, s, 1, 4);
    float a  = __fadd_rn(s, u);
    float b2 = __shfl_down_sync(gm, a, 2, 4);
    if (j == 0 && o < O) nrm[o] = sqrtf(__fadd_rn(a, b2));
}

// ---------------- scale + transpose: Wt[c][o] = fdiv(fmul(g,v), norm) ------
__global__ void scale_kernel(const float* __restrict__ v, const float* __restrict__ g,
                             const float* __restrict__ nrm, float* __restrict__ Wt,
                             int O, int C, int ldw) {
    __shared__ float tile[32][33];
    int c0 = blockIdx.x * 32, o0 = blockIdx.y * 32;
    int tx = threadIdx.x, ty = threadIdx.y;
    #pragma unroll
    for (int jj = 0; jj < 32; jj += 8) {
        int o = o0 + ty + jj, c = c0 + tx;
        if (o < O && c < C)
            tile[ty + jj][tx] = __fdiv_rn(__fmul_rn(g[o], v[(size_t)o * C + c]), nrm[o]);
    }
    __syncthreads();
    #pragma unroll
    for (int jj = 0; jj < 32; jj += 8) {
        int c = c0 + ty + jj, o = o0 + tx;
        if (o < O && c < C)
            Wt[(size_t)c * ldw + o] = tile[tx][ty + jj];
    }
}

// ---------------- build nonzero index lists + per-subchunk counts ----------
__global__ void build_kernel(const float* __restrict__ x, unsigned short* __restrict__ idx,
                             int* __restrict__ cntS, int K) {
    int warp = threadIdx.x >> 5, lane = threadIdx.x & 31;
    int row = blockIdx.x * 8 + warp;
    const float* xr = x + (size_t)row * K;
    unsigned short* ir = idx + (size_t)row * K;
    int pos = 0; int pcnt = 0;
    for (int k0 = 0; k0 < K; k0 += 32) {
        int k = k0 + lane;
        float vv = (k < K) ? xr[k] : 0.0f;
        unsigned m = __ballot_sync(0xffffffffu, vv != 0.0f);
        if (vv != 0.0f) {
            int off = pos + __popc(m & ((1u << lane) - 1u));
            ir[off] = (unsigned short)k;
        }
        int s0 = k0 / SC, s1 = (k0 + 31) / SC;
        if (s0 == s1) {
            if (lane == s0) pcnt += __popc(m);
        } else {
            int bnd = s1 * SC;
            unsigned low = (1u << (bnd - k0)) - 1u;
            if (lane == s0) pcnt += __popc(m & low);
            if (lane == s1) pcnt += __popc(m & ~low);
        }
        pos += __popc(m);
    }
    if (lane < NSMAX) cntS[row * NSMAX + lane] = pcnt;
}

// ---------------- sparse accumulate v3 ------------------------------------
// Z[row, o] = sum_{c in nz(row)} W[c][o].  Bit-exact panel structure: per KC
// panel an ascending-c fadd chain (continued across the two SC sub-stages),
// panels folded by fadd.  Warp covers 128 cols (float4/thread) -> each row
// walked only 512/128 = 4x total (the minimum).
#define OT  128     // output columns per block / warp
#define RPB 64      // rows per block
#define RPW 4       // rows per warp (16 warps)

extern __shared__ float Ws[];   // [SC][OT] = 63488 bytes

__global__ __launch_bounds__(512, 2)
void spmm_kernel(const unsigned short* __restrict__ idx, const int* __restrict__ cntS,
                 const float* __restrict__ W, float* __restrict__ Z,
                 int K, int NP, int ldw, int ldc) {
    const int tid  = threadIdx.x;
    const int lane = tid & 31;
    const int warp = tid >> 5;               // 0..15
    const int row0 = blockIdx.x * RPB + warp * RPW;
    const int o0   = blockIdx.y * OT;
    const int ocol = lane * 4;

    float4 acc[RPW];
    int pos[RPW];
    #pragma unroll
    for (int j = 0; j < RPW; j++) { acc[j] = make_float4(0.f,0.f,0.f,0.f); pos[j] = 0; }

    for (int p = 0; p < NP; p++) {
        const int ps = p * KC;
        float4 accP[RPW];
        #pragma unroll
        for (int j = 0; j < RPW; j++) accP[j] = make_float4(0.f,0.f,0.f,0.f);

        #pragma unroll
        for (int h = 0; h < 2; h++) {
            const int ss = ps + h * SC;
            if (ss >= K) break;
            int slen = K - ss; if (slen > SC) slen = SC;
            // cooperative sub-panel load: W[ss..ss+slen) x [o0..o0+128)
            for (int i4 = tid; i4 < slen * (OT / 4); i4 += 512) {
                int r = i4 >> 5, c4 = (i4 & 31) << 2;
                *(float4*)&Ws[r * OT + c4] =
                    *(const float4*)(W + (size_t)(ss + r) * ldw + o0 + c4);
            }
            __syncthreads();
            const int sub = p * 2 + h;
            #pragma unroll
            for (int j = 0; j < RPW; j++) {
                const int row = row0 + j;
                const int cnt = cntS[row * NSMAX + sub];
                const unsigned short* ip = idx + (size_t)row * K + pos[j];
                float4 a = accP[j];
                for (int i = 0; i < cnt; i++) {
                    int c = ip[i];
                    float4 wv = *(const float4*)&Ws[(c - ss) * OT + ocol];
                    a.x = __fadd_rn(a.x, wv.x);
                    a.y = __fadd_rn(a.y, wv.y);
                    a.z = __fadd_rn(a.z, wv.z);
                    a.w = __fadd_rn(a.w, wv.w);
                }
                accP[j] = a;
                pos[j] += cnt;
            }
            __syncthreads();
        }
        #pragma unroll
        for (int j = 0; j < RPW; j++) {
            acc[j].x = __fadd_rn(acc[j].x, accP[j].x);
            acc[j].y = __fadd_rn(acc[j].y, accP[j].y);
            acc[j].z = __fadd_rn(acc[j].z, accP[j].z);
            acc[j].w = __fadd_rn(acc[j].w, accP[j].w);
        }
    }
    #pragma unroll
    for (int j = 0; j < RPW; j++)
        *(float4*)(Z + (size_t)(row0 + j) * ldc + o0 + ocol) = acc[j];
}

// ---------------- LIF scan + delay, 512-wide layers ----------------
__global__ void scan512_kernel(const float* __restrict__ z, float* __restrict__ sd,
                               const int* __restrict__ delay, unsigned long long* cnt) {
    int tid = blockIdx.x * blockDim.x + threadIdx.x;  // 16384
    int o = tid & 511;
    int b = tid >> 9;
    int d = delay[o];
    const float* zp = z  + (size_t)b * TSTEPS * 512 + o;
    float*       sp = sd + (size_t)b * TSTEPS * 512 + o;
    float cur = 0.0f, vol = 0.0f;
    unsigned hist = 0u;
    int c = 0;
    for (int t = 0; t < TSTEPS; t++) {
        cur = fmaf(cur, 0.75f, zp[(size_t)t * 512]);
        float v = fmaf(vol, 0.97f, cur);
        int s = (__fadd_rn(v, -1.25f) >= 0.0f);
        vol = s ? 0.0f : v;
        hist = (hist << 1) | (unsigned)s;
        int sv = (t >= d) ? (int)((hist >> d) & 1u) : 0;
        sp[(size_t)t * 512] = (float)sv;
        c += sv;
    }
    atomicAdd(cnt, (unsigned long long)c);
}

// ---------------- LIF scan + delay, output layer (z ld = 128) --------------
__global__ void scan_out_kernel(const float* __restrict__ z, float* __restrict__ out,
                                const int* __restrict__ delay, unsigned long long* cnt) {
    int tid = blockIdx.x * blockDim.x + threadIdx.x;
    if (tid >= BATCH * O3) return;
    int o = tid % O3;
    int b = tid / O3;
    int d = delay[o];
    const float* zp = z + (size_t)b * TSTEPS * O3PAD + o;
    float* op = out + (size_t)b * O3 * TSTEPS + (size_t)o * TSTEPS;
    float cur = 0.0f, vol = 0.0f;
    unsigned hist = 0u;
    int c = 0;
    for (int t = 0; t < TSTEPS; t++) {
        cur = fmaf(cur, 0.75f, zp[(size_t)t * O3PAD]);
        float v = fmaf(vol, 0.97f, cur);
        int s = (__fadd_rn(v, -1.25f) >= 0.0f);
        vol = s ? 0.0f : v;
        hist = (hist << 1) | (unsigned)s;
        int sv = (t >= d) ? (int)((hist >> d) & 1u) : 0;
        op[t] = (float)sv;
        c += sv;
    }
    atomicAdd(cnt, (unsigned long long)c);
}

// ---------------- finalize counts ----------------
__global__ void finalize_kernel(float* out) {
    if (threadIdx.x == 0) {
        out[96000] = __fdiv_rn((float)g_cnt[0], 4915200.0f);
        out[96001] = __fdiv_rn((float)g_cnt[1], 4915200.0f);
        out[96002] = __fdiv_rn((float)g_cnt[2], 96000.0f);
    }
}

// ---------------- launch ----------------
extern "C" void kernel_launch(void* const* d_in, const int* in_sizes, int n_in,
                              void* d_out, int out_size) {
    const float* spike = (const float*)d_in[0];
    const float* v1 = (const float*)d_in[1];
    const float* g1 = (const float*)d_in[2];
    const float* v2 = (const float*)d_in[3];
    const float* g2 = (const float*)d_in[4];
    const float* v3 = (const float*)d_in[5];
    const float* g3 = (const float*)d_in[6];
    const int*   d1 = (const int*)d_in[7];
    const int*   d2 = (const int*)d_in[8];
    const int*   d3 = (const int*)d_in[9];
    float* out = (float*)d_out;

    float *x1, *z, *s1, *s2, *W1t, *W2t, *W3t, *nrm;
    unsigned short *idx1, *idx2;
    int* cntS;
    unsigned long long* cnt;
    cudaGetSymbolAddress((void**)&x1,  g_x1);
    cudaGetSymbolAddress((void**)&z,   g_z);
    cudaGetSymbolAddress((void**)&s1,  g_s1);
    cudaGetSymbolAddress((void**)&s2,  g_s2);
    cudaGetSymbolAddress((void**)&W1t, g_W1t);
    cudaGetSymbolAddress((void**)&W2t, g_W2t);
    cudaGetSymbolAddress((void**)&W3t, g_W3t);
    cudaGetSymbolAddress((void**)&nrm, g_norm);
    cudaGetSymbolAddress((void**)&idx1, g_idx1);
    cudaGetSymbolAddress((void**)&idx2, g_idx2);
    cudaGetSymbolAddress((void**)&cntS, g_cntS);
    cudaGetSymbolAddress((void**)&cnt, g_cnt);

    static int smem_set = 0;
    if (!smem_set) {
        cudaFuncSetAttribute(spmm_kernel, cudaFuncAttributeMaxDynamicSharedMemorySize,
                             SC * OT * (int)sizeof(float));
        smem_set = 1;
    }
    const int SPMM_SMEM = SC * OT * (int)sizeof(float);  // 63488

    init_kernel<<<64, 256>>>();

    {
        dim3 grid((TSTEPS + 31) / 32, (CIN + 31) / 32, BATCH);
        transpose_kernel<<<grid, dim3(32, 8)>>>(spike);
    }

    // ---- layer 1 ----
    norm4_kernel<<<(O1 * 4) / 256, 256>>>(v1, nrm, O1, CIN);
    scale_kernel<<<dim3((CIN + 31) / 32, O1 / 32), dim3(32, 8)>>>(v1, g1, nrm, W1t, O1, CIN, O1);
    build_kernel<<<MROWS / 8, 256>>>(x1, idx1, cntS, CIN);
    spmm_kernel<<<dim3(MROWS / RPB, O1 / OT), 512, SPMM_SMEM>>>(idx1, cntS, W1t, z, CIN, 10, O1, O1);
    scan512_kernel<<<(BATCH * O1) / 256, 256>>>(z, s1, d1, cnt + 0);

    // ---- layer 2 ----
    norm4_kernel<<<(O2 * 4) / 256, 256>>>(v2, nrm, O2, O1);
    scale_kernel<<<dim3(O1 / 32, O2 / 32), dim3(32, 8)>>>(v2, g2, nrm, W2t, O2, O1, O2);
    build_kernel<<<MROWS / 8, 256>>>(s1, idx2, cntS, O1);
    spmm_kernel<<<dim3(MROWS / RPB, O2 / OT), 512, SPMM_SMEM>>>(idx2, cntS, W2t, z, O1, 3, O2, O2);
    scan512_kernel<<<(BATCH * O2) / 256, 256>>>(z, s2, d2, cnt + 1);

    // ---- layer 3 (N padded to 128) ----
    norm4_kernel<<<1, 128>>>(v3, nrm, O3, O2);
    scale_kernel<<<dim3(O2 / 32, 1), dim3(32, 8)>>>(v3, g3, nrm, W3t, O3, O2, O3PAD);
    build_kernel<<<MROWS / 8, 256>>>(s2, idx2, cntS, O2);
    spmm_kernel<<<dim3(MROWS / RPB, 1), 512, SPMM_SMEM>>>(idx2, cntS, W3t, z, O2, 3, O3PAD, O3PAD);
    scan_out_kernel<<<2, 256>>>(z, out, d3, cnt + 2);

    finalize_kernel<<<1, 32>>>(out);
}

// round 9
// speedup vs baseline: 2.7558x; 1.1286x over previous
#include <cuda_runtime.h>
#include <cuda_bf16.h>
#include <math.h>
#include <stdint.h>

// Problem constants
#define BATCH 32
#define TSTEPS 300
#define CIN   2312        // 34*34*2
#define O1    512
#define O2    512
#define O3    10
#define O3PAD 128
#define MROWS (BATCH*TSTEPS)   // 9600
#define KC    248         // Eigen accumulation panel (bit-exactness anchor)
#define SC    124         // smem staging sub-panel (2 per KC panel)
#define NSMAX 19
#define CW1   73          // mask words per row, layer1 (ceil(2312/32))
#define CW2   16          // mask words per row, layers 2/3 (512/32)

// ---------------- static device scratch ----------------
__device__ float g_z  [ (size_t)BATCH*TSTEPS*O1  ];
__device__ float g_W1t[ (size_t)CIN*O1 ];
__device__ float g_W2t[ (size_t)O1*O2 ];
__device__ float g_W3t[ (size_t)O2*O3PAD ];
__device__ float g_norm[512];
__device__ unsigned g_mask1[(size_t)MROWS*CW1];
__device__ unsigned g_mask2[(size_t)MROWS*CW2];
__device__ unsigned short g_idx1[(size_t)MROWS*CIN];
__device__ unsigned short g_idx2[(size_t)MROWS*O1];
__device__ int g_cntS[(size_t)MROWS*NSMAX];
__device__ unsigned long long g_cnt[3];

// ---------------- init ----------------
__global__ void init_kernel() {
    int tid = blockIdx.x * blockDim.x + threadIdx.x;
    if (tid < 3) g_cnt[tid] = 0ull;
    for (int i = tid; i < O2 * O3PAD; i += gridDim.x * blockDim.x)
        g_W3t[i] = 0.0f;
}

// ---------------- transpose spikes -> bitmask [B,T,CW1] --------------------
__global__ void transpose_mask_kernel(const float* __restrict__ in) {
    __shared__ float tile[32][33];
    int b  = blockIdx.z;
    int t0 = blockIdx.x * 32;
    int cw = blockIdx.y;             // 32-c word index
    int c0 = cw * 32;
    int tx = threadIdx.x, ty = threadIdx.y;   // (32,8)
    const float* inb = in + (size_t)b * CIN * TSTEPS;
    int t = t0 + tx;
    #pragma unroll
    for (int j = 0; j < 32; j += 8) {
        int c = c0 + ty + j;
        float v = 0.0f;
        if (t < TSTEPS && c < CIN) v = inb[(size_t)c * TSTEPS + t];
        tile[ty + j][tx] = v;
    }
    __syncthreads();
    // now warp lanes tx = c-lane for row t2
    #pragma unroll
    for (int j = 0; j < 32; j += 8) {
        int t2 = t0 + ty + j;
        float v = tile[tx][ty + j];
        unsigned word = __ballot_sync(0xffffffffu, v != 0.0f);
        if (tx == 0 && t2 < TSTEPS)
            g_mask1[(size_t)(b * TSTEPS + t2) * CW1 + cw] = word;
    }
    __syncthreads();
}

// ---------------- norm: NEON 4-lane reduce, 4 threads per row -------------
__global__ void norm4_kernel(const float* __restrict__ v, float* __restrict__ nrm,
                             int O, int C) {
    int t = blockIdx.x * blockDim.x + threadIdx.x;
    int j = t & 3;
    int o = t >> 2;
    int oc = (o < O) ? o : (O - 1);
    const float* vr = v + (size_t)oc * C;
    float s = 0.0f;
    for (int c = j; c < C; c += 4)
        s = __fadd_rn(s, __fmul_rn(vr[c], vr[c]));
    unsigned gm = 0xFu << ((((unsigned)t & 31u) >> 2) << 2);
    float u  = __shfl_down_sync(gm, s, 1, 4);
    float a  = __fadd_rn(s, u);
    float b2 = __shfl_down_sync(gm, a, 2, 4);
    if (j == 0 && o < O) nrm[o] = sqrtf(__fadd_rn(a, b2));
}

// ---------------- scale + transpose: Wt[c][o] = fdiv(fmul(g,v), norm) ------
__global__ void scale_kernel(const float* __restrict__ v, const float* __restrict__ g,
                             const float* __restrict__ nrm, float* __restrict__ Wt,
                             int O, int C, int ldw) {
    __shared__ float tile[32][33];
    int c0 = blockIdx.x * 32, o0 = blockIdx.y * 32;
    int tx = threadIdx.x, ty = threadIdx.y;
    #pragma unroll
    for (int jj = 0; jj < 32; jj += 8) {
        int o = o0 + ty + jj, c = c0 + tx;
        if (o < O && c < C)
            tile[ty + jj][tx] = __fdiv_rn(__fmul_rn(g[o], v[(size_t)o * C + c]), nrm[o]);
    }
    __syncthreads();
    #pragma unroll
    for (int jj = 0; jj < 32; jj += 8) {
        int c = c0 + ty + jj, o = o0 + tx;
        if (o < O && c < C)
            Wt[(size_t)c * ldw + o] = tile[tx][ty + jj];
    }
}

// ---------------- build idx lists + subchunk counts from bitmasks ----------
// Warp per row.  Produces identical idx / cntS as the dense-scan builder.
__global__ void buildm_kernel(const unsigned* __restrict__ mask,
                              unsigned short* __restrict__ idx,
                              int* __restrict__ cntS, int NW, int K, int NS) {
    __shared__ unsigned sw[8][80];
    int warp = threadIdx.x >> 5, lane = threadIdx.x & 31;
    int row = blockIdx.x * 8 + warp;
    const unsigned* mr = mask + (size_t)row * NW;
    for (int w = lane; w < NW; w += 32) sw[warp][w] = mr[w];
    __syncwarp();

    unsigned short* ir = idx + (size_t)row * K;
    int pos = 0;
    int ngroups = (NW + 31) >> 5;
    for (int g = 0; g < ngroups; g++) {
        int w = g * 32 + lane;
        unsigned word = (w < NW) ? sw[warp][w] : 0u;
        int pc = __popc(word);
        // inclusive warp scan of pc
        int scan = pc;
        #pragma unroll
        for (int off = 1; off < 32; off <<= 1) {
            int n = __shfl_up_sync(0xffffffffu, scan, off);
            if (lane >= off) scan += n;
        }
        int base = pos + (scan - pc);
        unsigned ww = word;
        int r = 0;
        while (ww) {
            int bit = __ffs(ww) - 1;
            ir[base + r] = (unsigned short)(32 * w + bit);
            r++;
            ww &= ww - 1u;
        }
        pos += __shfl_sync(0xffffffffu, scan, 31);
    }
    // per-subchunk (SC=124) counts
    if (lane < NS) {
        int start = lane * SC;
        int end = start + SC; if (end > K) end = K;
        int wlo = start >> 5, whi = (end - 1) >> 5;
        int cnt = 0;
        for (int w = wlo; w <= whi; w++) {
            unsigned m = sw[warp][w];
            int cbase = w << 5;
            if (cbase < start) m &= ~((1u << (start - cbase)) - 1u);
            int rem = end - cbase;
            if (rem < 32) m &= (1u << rem) - 1u;
            cnt += __popc(m);
        }
        cntS[row * NSMAX + lane] = cnt;
    }
}

// ---------------- sparse accumulate (unchanged from R8; bit-exact core) ----
#define OT  128
#define RPB 64
#define RPW 4

extern __shared__ float Ws[];   // [SC][OT] = 63488 bytes

__global__ __launch_bounds__(512, 2)
void spmm_kernel(const unsigned short* __restrict__ idx, const int* __restrict__ cntS,
                 const float* __restrict__ W, float* __restrict__ Z,
                 int K, int NP, int ldw, int ldc) {
    const int tid  = threadIdx.x;
    const int lane = tid & 31;
    const int warp = tid >> 5;
    const int row0 = blockIdx.x * RPB + warp * RPW;
    const int o0   = blockIdx.y * OT;
    const int ocol = lane * 4;

    float4 acc[RPW];
    int pos[RPW];
    #pragma unroll
    for (int j = 0; j < RPW; j++) { acc[j] = make_float4(0.f,0.f,0.f,0.f); pos[j] = 0; }

    for (int p = 0; p < NP; p++) {
        const int ps = p * KC;
        float4 accP[RPW];
        #pragma unroll
        for (int j = 0; j < RPW; j++) accP[j] = make_float4(0.f,0.f,0.f,0.f);

        #pragma unroll
        for (int h = 0; h < 2; h++) {
            const int ss = ps + h * SC;
            if (ss >= K) break;
            int slen = K - ss; if (slen > SC) slen = SC;
            for (int i4 = tid; i4 < slen * (OT / 4); i4 += 512) {
                int r = i4 >> 5, c4 = (i4 & 31) << 2;
                *(float4*)&Ws[r * OT + c4] =
                    *(const float4*)(W + (size_t)(ss + r) * ldw + o0 + c4);
            }
            __syncthreads();
            const int sub = p * 2 + h;
            #pragma unroll
            for (int j = 0; j < RPW; j++) {
                const int row = row0 + j;
                const int cnt = cntS[row * NSMAX + sub];
                const unsigned short* ip = idx + (size_t)row * K + pos[j];
                float4 a = accP[j];
                for (int i = 0; i < cnt; i++) {
                    int c = ip[i];
                    float4 wv = *(const float4*)&Ws[(c - ss) * OT + ocol];
                    a.x = __fadd_rn(a.x, wv.x);
                    a.y = __fadd_rn(a.y, wv.y);
                    a.z = __fadd_rn(a.z, wv.z);
                    a.w = __fadd_rn(a.w, wv.w);
                }
                accP[j] = a;
                pos[j] += cnt;
            }
            __syncthreads();
        }
        #pragma unroll
        for (int j = 0; j < RPW; j++) {
            acc[j].x = __fadd_rn(acc[j].x, accP[j].x);
            acc[j].y = __fadd_rn(acc[j].y, accP[j].y);
            acc[j].z = __fadd_rn(acc[j].z, accP[j].z);
            acc[j].w = __fadd_rn(acc[j].w, accP[j].w);
        }
    }
    #pragma unroll
    for (int j = 0; j < RPW; j++)
        *(float4*)(Z + (size_t)(row0 + j) * ldc + o0 + ocol) = acc[j];
}

// ---------------- LIF scan, 512-wide: emits next-layer bitmask -------------
// Thread per (b,o); warp = 32 consecutive o.  Unroll-4 prefetch of z (MLP=4).
__global__ void scan512_kernel(const float* __restrict__ z, unsigned* __restrict__ maskN,
                               const int* __restrict__ delay, unsigned long long* cnt) {
    int tid = blockIdx.x * blockDim.x + threadIdx.x;  // 16384
    int o = tid & 511;
    int b = tid >> 9;
    int lane = tid & 31;
    int d = delay[o];
    const float* zp = z + (size_t)b * TSTEPS * 512 + o;
    unsigned* mw = maskN + (size_t)b * TSTEPS * CW2 + (o >> 5);
    float cur = 0.0f, vol = 0.0f;
    unsigned hist = 0u;
    int c = 0;
    for (int t = 0; t < TSTEPS; t += 4) {
        float za[4];
        #pragma unroll
        for (int u = 0; u < 4; u++) za[u] = zp[(size_t)(t + u) * 512];
        #pragma unroll
        for (int u = 0; u < 4; u++) {
            cur = fmaf(cur, 0.75f, za[u]);
            float v = fmaf(vol, 0.97f, cur);
            int s = (__fadd_rn(v, -1.25f) >= 0.0f);
            vol = s ? 0.0f : v;
            hist = (hist << 1) | (unsigned)s;
            int tt = t + u;
            int sv = (tt >= d) ? (int)((hist >> d) & 1u) : 0;
            unsigned word = __ballot_sync(0xffffffffu, sv);
            if (lane == 0) mw[(size_t)tt * CW2] = word;
            c += sv;
        }
    }
    atomicAdd(cnt, (unsigned long long)c);
}

// ---------------- LIF scan, output layer (z ld = O3PAD) --------------------
__global__ void scan_out_kernel(const float* __restrict__ z, float* __restrict__ out,
                                const int* __restrict__ delay, unsigned long long* cnt) {
    int tid = blockIdx.x * blockDim.x + threadIdx.x;
    if (tid >= BATCH * O3) return;
    int o = tid % O3;
    int b = tid / O3;
    int d = delay[o];
    const float* zp = z + (size_t)b * TSTEPS * O3PAD + o;
    float* op = out + (size_t)b * O3 * TSTEPS + (size_t)o * TSTEPS;
    float cur = 0.0f, vol = 0.0f;
    unsigned hist = 0u;
    int c = 0;
    for (int t = 0; t < TSTEPS; t += 4) {
        float za[4];
        #pragma unroll
        for (int u = 0; u < 4; u++) za[u] = zp[(size_t)(t + u) * O3PAD];
        #pragma unroll
        for (int u = 0; u < 4; u++) {
            cur = fmaf(cur, 0.75f, za[u]);
            float v = fmaf(vol, 0.97f, cur);
            int s = (__fadd_rn(v, -1.25f) >= 0.0f);
            vol = s ? 0.0f : v;
            hist = (hist << 1) | (unsigned)s;
            int tt = t + u;
            int sv = (tt >= d) ? (int)((hist >> d) & 1u) : 0;
            op[tt] = (float)sv;
            c += sv;
        }
    }
    atomicAdd(cnt, (unsigned long long)c);
}

// ---------------- finalize counts ----------------
__global__ void finalize_kernel(float* out) {
    if (threadIdx.x == 0) {
        out[96000] = __fdiv_rn((float)g_cnt[0], 4915200.0f);
        out[96001] = __fdiv_rn((float)g_cnt[1], 4915200.0f);
        out[96002] = __fdiv_rn((float)g_cnt[2], 96000.0f);
    }
}

// ---------------- launch ----------------
extern "C" void kernel_launch(void* const* d_in, const int* in_sizes, int n_in,
                              void* d_out, int out_size) {
    const float* spike = (const float*)d_in[0];
    const float* v1 = (const float*)d_in[1];
    const float* g1 = (const float*)d_in[2];
    const float* v2 = (const float*)d_in[3];
    const float* g2 = (const float*)d_in[4];
    const float* v3 = (const float*)d_in[5];
    const float* g3 = (const float*)d_in[6];
    const int*   d1 = (const int*)d_in[7];
    const int*   d2 = (const int*)d_in[8];
    const int*   d3 = (const int*)d_in[9];
    float* out = (float*)d_out;

    float *z, *W1t, *W2t, *W3t, *nrm;
    unsigned *mask1, *mask2;
    unsigned short *idx1, *idx2;
    int* cntS;
    unsigned long long* cnt;
    cudaGetSymbolAddress((void**)&z,   g_z);
    cudaGetSymbolAddress((void**)&W1t, g_W1t);
    cudaGetSymbolAddress((void**)&W2t, g_W2t);
    cudaGetSymbolAddress((void**)&W3t, g_W3t);
    cudaGetSymbolAddress((void**)&nrm, g_norm);
    cudaGetSymbolAddress((void**)&mask1, g_mask1);
    cudaGetSymbolAddress((void**)&mask2, g_mask2);
    cudaGetSymbolAddress((void**)&idx1, g_idx1);
    cudaGetSymbolAddress((void**)&idx2, g_idx2);
    cudaGetSymbolAddress((void**)&cntS, g_cntS);
    cudaGetSymbolAddress((void**)&cnt, g_cnt);

    static int smem_set = 0;
    if (!smem_set) {
        cudaFuncSetAttribute(spmm_kernel, cudaFuncAttributeMaxDynamicSharedMemorySize,
                             SC * OT * (int)sizeof(float));
        smem_set = 1;
    }
    const int SPMM_SMEM = SC * OT * (int)sizeof(float);  // 63488

    init_kernel<<<64, 256>>>();

    {
        dim3 grid((TSTEPS + 31) / 32, CW1, BATCH);
        transpose_mask_kernel<<<grid, dim3(32, 8)>>>(spike);
    }

    // ---- layer 1 ----
    norm4_kernel<<<(O1 * 4) / 256, 256>>>(v1, nrm, O1, CIN);
    scale_kernel<<<dim3((CIN + 31) / 32, O1 / 32), dim3(32, 8)>>>(v1, g1, nrm, W1t, O1, CIN, O1);
    buildm_kernel<<<MROWS / 8, 256>>>(mask1, idx1, cntS, CW1, CIN, 19);
    spmm_kernel<<<dim3(MROWS / RPB, O1 / OT), 512, SPMM_SMEM>>>(idx1, cntS, W1t, z, CIN, 10, O1, O1);
    scan512_kernel<<<(BATCH * O1) / 256, 256>>>(z, mask2, d1, cnt + 0);

    // ---- layer 2 ----
    norm4_kernel<<<(O2 * 4) / 256, 256>>>(v2, nrm, O2, O1);
    scale_kernel<<<dim3(O1 / 32, O2 / 32), dim3(32, 8)>>>(v2, g2, nrm, W2t, O2, O1, O2);
    buildm_kernel<<<MROWS / 8, 256>>>(mask2, idx2, cntS, CW2, O1, 5);
    spmm_kernel<<<dim3(MROWS / RPB, O2 / OT), 512, SPMM_SMEM>>>(idx2, cntS, W2t, z, O1, 3, O2, O2);
    scan512_kernel<<<(BATCH * O2) / 256, 256>>>(z, mask2, d2, cnt + 1);

    // ---- layer 3 (N padded to 128) ----
    norm4_kernel<<<1, 128>>>(v3, nrm, O3, O2);
    scale_kernel<<<dim3(O2 / 32, 1), dim3(32, 8)>>>(v3, g3, nrm, W3t, O3, O2, O3PAD);
    buildm_kernel<<<MROWS / 8, 256>>>(mask2, idx2, cntS, CW2, O2, 5);
    spmm_kernel<<<dim3(MROWS / RPB, 1), 512, SPMM_SMEM>>>(idx2, cntS, W3t, z, O2, 3, O3PAD, O3PAD);
    scan_out_kernel<<<2, 256>>>(z, out, d3, cnt + 2);

    finalize_kernel<<<1, 32>>>(out);
}

// round 10
// speedup vs baseline: 2.9524x; 1.0714x over previous
#include <cuda_runtime.h>
#include <cuda_bf16.h>
#include <math.h>
#include <stdint.h>

// Problem constants
#define BATCH 32
#define TSTEPS 300
#define CIN   2312        // 34*34*2
#define O1    512
#define O2    512
#define O3    10
#define O3PAD 128
#define MROWS (BATCH*TSTEPS)   // 9600
#define KC    248         // Eigen accumulation panel (bit-exactness anchor)
#define SC    124         // smem staging sub-panel (2 per KC panel)
#define NSMAX 19
#define CW1   73          // mask words per row, layer1
#define CW2   16          // mask words per row, layers 2/3

// ---------------- static device scratch ----------------
__device__ float g_z  [ (size_t)BATCH*TSTEPS*O1  ];
__device__ float g_W1t[ (size_t)CIN*O1 ];
__device__ float g_W2t[ (size_t)O1*O2 ];
__device__ float g_W3t[ (size_t)O2*O3PAD ];
__device__ float g_norm[512];
__device__ unsigned g_mask1[(size_t)MROWS*CW1];
__device__ unsigned g_mask2[(size_t)MROWS*CW2];
__device__ unsigned short g_idx1[(size_t)MROWS*CIN];
__device__ unsigned short g_idx2[(size_t)MROWS*O1];
__device__ int g_cntS[(size_t)MROWS*NSMAX];
__device__ unsigned long long g_cnt[3];

// ---------------- cp.async helpers ----------------
__device__ __forceinline__ void cp_async16(uint32_t saddr, const void* gaddr) {
    asm volatile("cp.async.cg.shared.global [%0], [%1], 16;" :: "r"(saddr), "l"(gaddr));
}
__device__ __forceinline__ void cp_commit() {
    asm volatile("cp.async.commit_group;");
}
template <int N> __device__ __forceinline__ void cp_wait() {
    asm volatile("cp.async.wait_group %0;" :: "n"(N));
}
__device__ __forceinline__ uint32_t smem_u32(const void* p) {
    return (uint32_t)__cvta_generic_to_shared(p);
}

// ---------------- init ----------------
__global__ void init_kernel() {
    int tid = blockIdx.x * blockDim.x + threadIdx.x;
    if (tid < 3) g_cnt[tid] = 0ull;
    for (int i = tid; i < O2 * O3PAD; i += gridDim.x * blockDim.x)
        g_W3t[i] = 0.0f;
}

// ---------------- transpose spikes -> bitmask [B,T,CW1] --------------------
__global__ void transpose_mask_kernel(const float* __restrict__ in) {
    __shared__ float tile[32][33];
    int b  = blockIdx.z;
    int t0 = blockIdx.x * 32;
    int cw = blockIdx.y;
    int c0 = cw * 32;
    int tx = threadIdx.x, ty = threadIdx.y;   // (32,8)
    const float* inb = in + (size_t)b * CIN * TSTEPS;
    int t = t0 + tx;
    #pragma unroll
    for (int j = 0; j < 32; j += 8) {
        int c = c0 + ty + j;
        float v = 0.0f;
        if (t < TSTEPS && c < CIN) v = inb[(size_t)c * TSTEPS + t];
        tile[ty + j][tx] = v;
    }
    __syncthreads();
    #pragma unroll
    for (int j = 0; j < 32; j += 8) {
        int t2 = t0 + ty + j;
        float v = tile[tx][ty + j];
        unsigned word = __ballot_sync(0xffffffffu, v != 0.0f);
        if (tx == 0 && t2 < TSTEPS)
            g_mask1[(size_t)(b * TSTEPS + t2) * CW1 + cw] = word;
    }
}

// ---------------- norm: NEON 4-lane reduce, 4 threads per row -------------
__global__ void norm4_kernel(const float* __restrict__ v, float* __restrict__ nrm,
                             int O, int C) {
    int t = blockIdx.x * blockDim.x + threadIdx.x;
    int j = t & 3;
    int o = t >> 2;
    int oc = (o < O) ? o : (O - 1);
    const float* vr = v + (size_t)oc * C;
    float s = 0.0f;
    for (int c = j; c < C; c += 4)
        s = __fadd_rn(s, __fmul_rn(vr[c], vr[c]));
    unsigned gm = 0xFu << ((((unsigned)t & 31u) >> 2) << 2);
    float u  = __shfl_down_sync(gm, s, 1, 4);
    float a  = __fadd_rn(s, u);
    float b2 = __shfl_down_sync(gm, a, 2, 4);
    if (j == 0 && o < O) nrm[o] = sqrtf(__fadd_rn(a, b2));
}

// ---------------- scale + transpose ----------------
__global__ void scale_kernel(const float* __restrict__ v, const float* __restrict__ g,
                             const float* __restrict__ nrm, float* __restrict__ Wt,
                             int O, int C, int ldw) {
    __shared__ float tile[32][33];
    int c0 = blockIdx.x * 32, o0 = blockIdx.y * 32;
    int tx = threadIdx.x, ty = threadIdx.y;
    #pragma unroll
    for (int jj = 0; jj < 32; jj += 8) {
        int o = o0 + ty + jj, c = c0 + tx;
        if (o < O && c < C)
            tile[ty + jj][tx] = __fdiv_rn(__fmul_rn(g[o], v[(size_t)o * C + c]), nrm[o]);
    }
    __syncthreads();
    #pragma unroll
    for (int jj = 0; jj < 32; jj += 8) {
        int c = c0 + ty + jj, o = o0 + tx;
        if (o < O && c < C)
            Wt[(size_t)c * ldw + o] = tile[tx][ty + jj];
    }
}

// ---------------- build idx lists + subchunk counts from bitmasks ----------
__global__ void buildm_kernel(const unsigned* __restrict__ mask,
                              unsigned short* __restrict__ idx,
                              int* __restrict__ cntS, int NW, int K, int NS) {
    __shared__ unsigned sw[8][80];
    int warp = threadIdx.x >> 5, lane = threadIdx.x & 31;
    int row = blockIdx.x * 8 + warp;
    const unsigned* mr = mask + (size_t)row * NW;
    for (int w = lane; w < NW; w += 32) sw[warp][w] = mr[w];
    __syncwarp();

    unsigned short* ir = idx + (size_t)row * K;
    int pos = 0;
    int ngroups = (NW + 31) >> 5;
    for (int g = 0; g < ngroups; g++) {
        int w = g * 32 + lane;
        unsigned word = (w < NW) ? sw[warp][w] : 0u;
        int pc = __popc(word);
        int scan = pc;
        #pragma unroll
        for (int off = 1; off < 32; off <<= 1) {
            int n = __shfl_up_sync(0xffffffffu, scan, off);
            if (lane >= off) scan += n;
        }
        int base = pos + (scan - pc);
        unsigned ww = word;
        int r = 0;
        while (ww) {
            int bit = __ffs(ww) - 1;
            ir[base + r] = (unsigned short)(32 * w + bit);
            r++;
            ww &= ww - 1u;
        }
        pos += __shfl_sync(0xffffffffu, scan, 31);
    }
    if (lane < NS) {
        int start = lane * SC;
        int end = start + SC; if (end > K) end = K;
        int wlo = start >> 5, whi = (end - 1) >> 5;
        int cnt = 0;
        for (int w = wlo; w <= whi; w++) {
            unsigned m = sw[warp][w];
            int cbase = w << 5;
            if (cbase < start) m &= ~((1u << (start - cbase)) - 1u);
            int rem = end - cbase;
            if (rem < 32) m &= (1u << rem) - 1u;
            cnt += __popc(m);
        }
        cntS[row * NSMAX + lane] = cnt;
    }
}

// ---------------- sparse accumulate v4: 1024 thr, cp.async double buffer ---
// Z[row, o] = sum_{c in nz(row)} W[c][o].  Bit-exact: per KC panel an
// ascending-c fadd chain (2 SC stages, fold after odd/final stage), panels
// folded by fadd.  Warp covers 128 cols (float4/thread).
#define OT  128
#define RPB 128
#define RPW 4       // 32 warps x 4 rows

extern __shared__ float Ws[];   // 2 x [SC][OT] = 126976 bytes

__global__ __launch_bounds__(1024)
void spmm_kernel(const unsigned short* __restrict__ idx, const int* __restrict__ cntS,
                 const float* __restrict__ W, float* __restrict__ Z,
                 int K, int NS, int ldw, int ldc) {
    const int tid  = threadIdx.x;
    const int lane = tid & 31;
    const int warp = tid >> 5;               // 0..31
    const int row0 = blockIdx.x * RPB + warp * RPW;
    const int o0   = blockIdx.y * OT;
    const int ocol = lane * 4;
    const uint32_t sbase = smem_u32(Ws);

    float4 acc[RPW], accP[RPW];
    int pos[RPW];
    #pragma unroll
    for (int j = 0; j < RPW; j++) {
        acc[j] = make_float4(0.f,0.f,0.f,0.f);
        accP[j] = make_float4(0.f,0.f,0.f,0.f);
        pos[j] = 0;
    }

    // prologue: stage 0 -> buffer 0
    {
        int slen = (K < SC) ? K : SC;
        for (int i4 = tid; i4 < slen * (OT / 4); i4 += 1024) {
            int r = i4 >> 5, c4 = (i4 & 31) << 2;
            cp_async16(sbase + (uint32_t)(r * OT + c4) * 4u,
                       W + (size_t)r * ldw + o0 + c4);
        }
        cp_commit();
    }

    int buf = 0;
    for (int s = 0; s < NS; s++) {
        // kick off next stage into other buffer, then wait for current
        if (s + 1 < NS) {
            int ss = (s + 1) * SC;
            int slen = K - ss; if (slen > SC) slen = SC;
            uint32_t bofs = (uint32_t)((buf ^ 1) * SC * OT) * 4u;
            for (int i4 = tid; i4 < slen * (OT / 4); i4 += 1024) {
                int r = i4 >> 5, c4 = (i4 & 31) << 2;
                cp_async16(sbase + bofs + (uint32_t)(r * OT + c4) * 4u,
                           W + (size_t)(ss + r) * ldw + o0 + c4);
            }
            cp_commit();
            cp_wait<1>();
        } else {
            cp_wait<0>();
        }
        __syncthreads();

        const int ss = s * SC;
        const float* Wb = Ws + buf * SC * OT;
        #pragma unroll
        for (int j = 0; j < RPW; j++) {
            const int row = row0 + j;
            const int cnt = cntS[row * NSMAX + s];
            const unsigned short* ip = idx + (size_t)row * K + pos[j];
            float4 a = accP[j];
            for (int i = 0; i < cnt; i++) {
                int c = ip[i];
                float4 wv = *(const float4*)&Wb[(c - ss) * OT + ocol];
                a.x = __fadd_rn(a.x, wv.x);
                a.y = __fadd_rn(a.y, wv.y);
                a.z = __fadd_rn(a.z, wv.z);
                a.w = __fadd_rn(a.w, wv.w);
            }
            accP[j] = a;
            pos[j] += cnt;
        }
        __syncthreads();   // all warps done with buf before it is refilled

        if ((s & 1) == 1 || s == NS - 1) {   // end of KC panel: fold
            #pragma unroll
            for (int j = 0; j < RPW; j++) {
                acc[j].x = __fadd_rn(acc[j].x, accP[j].x);
                acc[j].y = __fadd_rn(acc[j].y, accP[j].y);
                acc[j].z = __fadd_rn(acc[j].z, accP[j].z);
                acc[j].w = __fadd_rn(acc[j].w, accP[j].w);
                accP[j] = make_float4(0.f,0.f,0.f,0.f);
            }
        }
        buf ^= 1;
    }
    #pragma unroll
    for (int j = 0; j < RPW; j++)
        *(float4*)(Z + (size_t)(row0 + j) * ldc + o0 + ocol) = acc[j];
}

// ---------------- LIF scan, 512-wide: emits next-layer bitmask -------------
__global__ void scan512_kernel(const float* __restrict__ z, unsigned* __restrict__ maskN,
                               const int* __restrict__ delay, unsigned long long* cnt) {
    int tid = blockIdx.x * blockDim.x + threadIdx.x;  // 16384
    int o = tid & 511;
    int b = tid >> 9;
    int lane = tid & 31;
    int d = delay[o];
    const float* zp = z + (size_t)b * TSTEPS * 512 + o;
    unsigned* mw = maskN + (size_t)b * TSTEPS * CW2 + (o >> 5);
    float cur = 0.0f, vol = 0.0f;
    unsigned hist = 0u;
    int c = 0;
    for (int t = 0; t < TSTEPS; t += 4) {
        float za[4];
        #pragma unroll
        for (int u = 0; u < 4; u++) za[u] = zp[(size_t)(t + u) * 512];
        #pragma unroll
        for (int u = 0; u < 4; u++) {
            cur = fmaf(cur, 0.75f, za[u]);
            float v = fmaf(vol, 0.97f, cur);
            int s = (__fadd_rn(v, -1.25f) >= 0.0f);
            vol = s ? 0.0f : v;
            hist = (hist << 1) | (unsigned)s;
            int tt = t + u;
            int sv = (tt >= d) ? (int)((hist >> d) & 1u) : 0;
            unsigned word = __ballot_sync(0xffffffffu, sv);
            if (lane == 0) mw[(size_t)tt * CW2] = word;
            c += sv;
        }
    }
    atomicAdd(cnt, (unsigned long long)c);
}

// ---------------- LIF scan, output layer (z ld = O3PAD) --------------------
__global__ void scan_out_kernel(const float* __restrict__ z, float* __restrict__ out,
                                const int* __restrict__ delay, unsigned long long* cnt) {
    int tid = blockIdx.x * blockDim.x + threadIdx.x;
    if (tid >= BATCH * O3) return;
    int o = tid % O3;
    int b = tid / O3;
    int d = delay[o];
    const float* zp = z + (size_t)b * TSTEPS * O3PAD + o;
    float* op = out + (size_t)b * O3 * TSTEPS + (size_t)o * TSTEPS;
    float cur = 0.0f, vol = 0.0f;
    unsigned hist = 0u;
    int c = 0;
    for (int t = 0; t < TSTEPS; t += 4) {
        float za[4];
        #pragma unroll
        for (int u = 0; u < 4; u++) za[u] = zp[(size_t)(t + u) * O3PAD];
        #pragma unroll
        for (int u = 0; u < 4; u++) {
            cur = fmaf(cur, 0.75f, za[u]);
            float v = fmaf(vol, 0.97f, cur);
            int s = (__fadd_rn(v, -1.25f) >= 0.0f);
            vol = s ? 0.0f : v;
            hist = (hist << 1) | (unsigned)s;
            int tt = t + u;
            int sv = (tt >= d) ? (int)((hist >> d) & 1u) : 0;
            op[tt] = (float)sv;
            c += sv;
        }
    }
    atomicAdd(cnt, (unsigned long long)c);
}

// ---------------- finalize counts ----------------
__global__ void finalize_kernel(float* out) {
    if (threadIdx.x == 0) {
        out[96000] = __fdiv_rn((float)g_cnt[0], 4915200.0f);
        out[96001] = __fdiv_rn((float)g_cnt[1], 4915200.0f);
        out[96002] = __fdiv_rn((float)g_cnt[2], 96000.0f);
    }
}

// ---------------- launch ----------------
extern "C" void kernel_launch(void* const* d_in, const int* in_sizes, int n_in,
                              void* d_out, int out_size) {
    const float* spike = (const float*)d_in[0];
    const float* v1 = (const float*)d_in[1];
    const float* g1 = (const float*)d_in[2];
    const float* v2 = (const float*)d_in[3];
    const float* g2 = (const float*)d_in[4];
    const float* v3 = (const float*)d_in[5];
    const float* g3 = (const float*)d_in[6];
    const int*   d1 = (const int*)d_in[7];
    const int*   d2 = (const int*)d_in[8];
    const int*   d3 = (const int*)d_in[9];
    float* out = (float*)d_out;

    float *z, *W1t, *W2t, *W3t, *nrm;
    unsigned *mask1, *mask2;
    unsigned short *idx1, *idx2;
    int* cntS;
    unsigned long long* cnt;
    cudaGetSymbolAddress((void**)&z,   g_z);
    cudaGetSymbolAddress((void**)&W1t, g_W1t);
    cudaGetSymbolAddress((void**)&W2t, g_W2t);
    cudaGetSymbolAddress((void**)&W3t, g_W3t);
    cudaGetSymbolAddress((void**)&nrm, g_norm);
    cudaGetSymbolAddress((void**)&mask1, g_mask1);
    cudaGetSymbolAddress((void**)&mask2, g_mask2);
    cudaGetSymbolAddress((void**)&idx1, g_idx1);
    cudaGetSymbolAddress((void**)&idx2, g_idx2);
    cudaGetSymbolAddress((void**)&cntS, g_cntS);
    cudaGetSymbolAddress((void**)&cnt, g_cnt);

    static int smem_set = 0;
    if (!smem_set) {
        cudaFuncSetAttribute(spmm_kernel, cudaFuncAttributeMaxDynamicSharedMemorySize,
                             2 * SC * OT * (int)sizeof(float));
        smem_set = 1;
    }
    const int SPMM_SMEM = 2 * SC * OT * (int)sizeof(float);  // 126976

    init_kernel<<<64, 256>>>();

    {
        dim3 grid((TSTEPS + 31) / 32, CW1, BATCH);
        transpose_mask_kernel<<<grid, dim3(32, 8)>>>(spike);
    }

    // ---- layer 1 (NS = ceil(2312/124) = 19) ----
    norm4_kernel<<<(O1 * 4) / 256, 256>>>(v1, nrm, O1, CIN);
    scale_kernel<<<dim3((CIN + 31) / 32, O1 / 32), dim3(32, 8)>>>(v1, g1, nrm, W1t, O1, CIN, O1);
    buildm_kernel<<<MROWS / 8, 256>>>(mask1, idx1, cntS, CW1, CIN, 19);
    spmm_kernel<<<dim3(MROWS / RPB, O1 / OT), 1024, SPMM_SMEM>>>(idx1, cntS, W1t, z, CIN, 19, O1, O1);
    scan512_kernel<<<(BATCH * O1) / 256, 256>>>(z, mask2, d1, cnt + 0);

    // ---- layer 2 (NS = ceil(512/124) = 5) ----
    norm4_kernel<<<(O2 * 4) / 256, 256>>>(v2, nrm, O2, O1);
    scale_kernel<<<dim3(O1 / 32, O2 / 32), dim3(32, 8)>>>(v2, g2, nrm, W2t, O2, O1, O2);
    buildm_kernel<<<MROWS / 8, 256>>>(mask2, idx2, cntS, CW2, O1, 5);
    spmm_kernel<<<dim3(MROWS / RPB, O2 / OT), 1024, SPMM_SMEM>>>(idx2, cntS, W2t, z, O1, 5, O2, O2);
    scan512_kernel<<<(BATCH * O2) / 256, 256>>>(z, mask2, d2, cnt + 1);

    // ---- layer 3 (N padded to 128) ----
    norm4_kernel<<<1, 128>>>(v3, nrm, O3, O2);
    scale_kernel<<<dim3(O2 / 32, 1), dim3(32, 8)>>>(v3, g3, nrm, W3t, O3, O2, O3PAD);
    buildm_kernel<<<MROWS / 8, 256>>>(mask2, idx2, cntS, CW2, O2, 5);
    spmm_kernel<<<dim3(MROWS / RPB, 1), 1024, SPMM_SMEM>>>(idx2, cntS, W3t, z, O2, 5, O3PAD, O3PAD);
    scan_out_kernel<<<2, 256>>>(z, out, d3, cnt + 2);

    finalize_kernel<<<1, 32>>>(out);
}